// round 14
// baseline (speedup 1.0000x reference)
#include <cuda_runtime.h>
#include <math.h>

// ---------------- problem constants ----------------
#define Bn    16
#define Nn    15
#define Tn    50
#define NA    121
#define NR    40
#define Gd    4840            // NA*NR
#define G2    9680            // 2*Gd
#define K30   30              // 2*Nn
#define CP    800             // columns = B*T exactly
#define NITER 50
#define GS    148             // chunks (1 CTA/SM)
#define GDC   33              // Gd rows per chunk; 148*33=4884 >= 4840, tail masked
#define GCH   66              // buildC / gram: G2 rows per chunk
#define TPB   416             // 13 warps; threads 0..399 own 2 cols each
#define NACT  400             // active threads in main loops

typedef unsigned long long u64;

// ---------------- scratch (static device memory; no allocs) ----------------
__device__ float dA[K30 * G2];            // 1.16 MB  row-major [k][g]
__device__ float dX[G2 * CP];             // 31 MB  [g][c]
__device__ float dC[G2 * CP];             // 31 MB  [g][c]
__device__ float dZ[K30 * CP];            // [k][c], pre-scaled by coef0
__device__ float dZpart[GS * K30 * CP];   // 14.2 MB split-K partials
__device__ float dYst[K30 * CP];          // stacked y [k][c]
__device__ float dM30[K30 * K30];         // Gram A A^T
__device__ float dGpart[GS * K30 * K30];  // gram partials
__device__ float dParams[4];              // [0]=coef0=1/lambda, [1]=thr=0.3/lambda
__device__ float dNpart[10 * CP];         // norm partials
__device__ int   dMinIdx[Bn];

// ---------------- f32x2 helpers ----------------
__device__ __forceinline__ u64 pack2(float a, float b) {
    u64 r; asm("mov.b64 %0, {%1,%2};" : "=l"(r) : "f"(a), "f"(b)); return r;
}
__device__ __forceinline__ void unpack2(u64 v, float& a, float& b) {
    asm("mov.b64 {%0,%1}, %2;" : "=f"(a), "=f"(b) : "l"(v));
}
__device__ __forceinline__ u64 fma2(u64 a, u64 b, u64 c) {
    u64 d; asm("fma.rn.f32x2 %0, %1, %2, %3;" : "=l"(d) : "l"(a), "l"(b), "l"(c)); return d;
}
__device__ __forceinline__ u64 add2(u64 a, u64 b) {
    u64 d; asm("add.rn.f32x2 %0, %1, %2;" : "=l"(d) : "l"(a), "l"(b)); return d;
}

// ---------------- prep kernels ----------------
__global__ void k_build_yst(const float* __restrict__ yr, const float* __restrict__ yi) {
    int idx = blockIdx.x * 256 + threadIdx.x;       // over K30*CP = 24000
    if (idx >= K30 * CP) return;
    int k = idx / CP, c = idx % CP;
    int b = c / Tn, t = c % Tn;
    float v;
    if (k < Nn) v = yr[(b * Nn + k) * Tn + t];
    else        v = yi[(b * Nn + (k - Nn)) * Tn + t];
    dYst[idx] = v;
}

__global__ void k_build_A(const float* __restrict__ Ar, const float* __restrict__ Ai) {
    int idx = blockIdx.x * 256 + threadIdx.x;       // over K30*G2
    if (idx >= K30 * G2) return;
    int k = idx / G2, g = idx % G2;
    float v;
    if (k < Nn) {
        v = (g < Gd) ? Ar[k * Gd + g] : -Ai[k * Gd + (g - Gd)];
    } else {
        int kk = k - Nn;
        v = (g < Gd) ? Ai[kk * Gd + g] : Ar[kk * Gd + (g - Gd)];
    }
    dA[idx] = v;
}

// Gram stage 1: per-chunk partial 30x30 Gram (grid GS, block 256)
__global__ void k_gram_part() {
    __shared__ float As[K30 * GCH];
    int tid = threadIdx.x, gs = blockIdx.x;
    int g0 = gs * GCH;
    for (int i = tid; i < K30 * GCH; i += 256) {
        int k = i / GCH, gl = i % GCH;
        int g = g0 + gl;
        As[i] = (g < G2) ? dA[k * G2 + g] : 0.0f;
    }
    __syncthreads();
    for (int p = tid; p < K30 * K30; p += 256) {
        int i = p / K30, j = p % K30;
        float s = 0.0f;
        #pragma unroll 6
        for (int gl = 0; gl < GCH; gl++)
            s += As[i * GCH + gl] * As[j * GCH + gl];
        dGpart[gs * (K30 * K30) + p] = s;
    }
}

// Gram stage 2: one warp per element, lanes split the 148 partials (shfl tree)
__global__ void k_gram_red() {
    int warp = (blockIdx.x * blockDim.x + threadIdx.x) >> 5;
    int lane = threadIdx.x & 31;
    if (warp >= K30 * K30) return;
    float s = 0.0f;
    for (int gs = lane; gs < GS; gs += 32)
        s += dGpart[gs * (K30 * K30) + warp];
    #pragma unroll
    for (int o = 16; o > 0; o >>= 1)
        s += __shfl_xor_sync(0xFFFFFFFFu, s, o);
    if (lane == 0) dM30[warp] = s;
}

// lambda_max via 12 matrix squarings (Frobenius-normalized) + Rayleigh quotient
__global__ void k_eig() {
    __shared__ float Ms[900];
    __shared__ float Mn[900];
    __shared__ float wsum[32];
    __shared__ float norm2;
    int t = threadIdx.x;
    int lane = t & 31, wid = t >> 5;
    if (t < 900) Ms[t] = dM30[t];
    __syncthreads();
    for (int it = 0; it < 12; it++) {
        float v = 0.0f;
        if (t < 900) {
            int i = t / K30, j = t % K30;
            #pragma unroll 6
            for (int k = 0; k < K30; k++) v += Ms[i * K30 + k] * Ms[k * K30 + j];
            Mn[t] = v;
        }
        float w = (t < 900) ? v * v : 0.0f;
        #pragma unroll
        for (int o = 16; o > 0; o >>= 1)
            w += __shfl_xor_sync(0xFFFFFFFFu, w, o);
        if (lane == 0) wsum[wid] = w;
        __syncthreads();
        if (wid == 0) {
            float x = wsum[lane];
            #pragma unroll
            for (int o = 16; o > 0; o >>= 1)
                x += __shfl_xor_sync(0xFFFFFFFFu, x, o);
            if (lane == 0) norm2 = x;
        }
        __syncthreads();
        float inv = rsqrtf(norm2);
        if (t < 900) Ms[t] = Mn[t] * inv;
        __syncthreads();
    }
    if (t == 0) {
        float v[K30]; float nv = 0.0f;
        for (int i = 0; i < K30; i++) {
            float s = 0.0f;
            for (int j = 0; j < K30; j++) s += Ms[i * K30 + j];
            v[i] = s; nv += s * s;
        }
        float inv = rsqrtf(nv);
        for (int i = 0; i < K30; i++) v[i] *= inv;
        float lam = 0.0f;
        for (int i = 0; i < K30; i++) {
            float w = 0.0f;
            for (int j = 0; j < K30; j++) w += dM30[i * K30 + j] * v[j];
            lam += v[i] * w;
        }
        dParams[0] = 1.0f / lam;   // coef0 = step/n
        dParams[1] = 0.3f / lam;   // thr  = mu*step
    }
}

// C = coef0 * A^T yst : grid GS, block TPB (one-time, G2-chunked)
__global__ void __launch_bounds__(TPB, 1) k_buildC() {
    __shared__ u64 As2[K30 * GCH];
    int tid = threadIdx.x, gs = blockIdx.x;
    int g0 = gs * GCH;
    for (int i = tid; i < K30 * GCH; i += TPB) {
        int k = i / GCH, gl = i % GCH;
        int g = g0 + gl;
        float a = (g < G2) ? dA[k * G2 + g] : 0.0f;
        As2[i] = pack2(a, a);
    }
    __syncthreads();
    int glN = G2 - g0;
    if (glN > GCH) glN = GCH;
    if (glN < 0) glN = 0;
    if (tid >= NACT) return;
    int c0 = tid * 2;
    u64 yreg[K30];
    #pragma unroll
    for (int k = 0; k < K30; k++)
        yreg[k] = *reinterpret_cast<const u64*>(&dYst[k * CP + c0]);
    float coef0 = dParams[0];
    for (int gl = 0; gl < glN; gl++) {
        u64 d0 = 0ULL, d1 = 0ULL;
        #pragma unroll
        for (int k = 0; k < K30; k += 2) {
            d0 = fma2(As2[k * GCH + gl],       yreg[k],     d0);
            d1 = fma2(As2[(k + 1) * GCH + gl], yreg[k + 1], d1);
        }
        float a0, b0, a1, b1;
        unpack2(d0, a0, b0); unpack2(d1, a1, b1);
        float2 ov; ov.x = coef0 * (a0 + a1); ov.y = coef0 * (b0 + b1);
        *reinterpret_cast<float2*>(&dC[(g0 + gl) * CP + c0]) = ov;
    }
}

// ---------------- fused iteration kernel (complex-paired, Karatsuba loop1) ----------------
// Loop 1 (conjugate dot, 3-mult Karatsuba):
//   d(g)    = M1 + M2,          M1 = sum ar*zr,  M2 = sum ai*zi
//   d(g+Gd) = M3 - M1 + M2,     M3 = sum (ar-ai)*(zr+zi)
//   -> 45 fma2/gl instead of 60 (25% off the FMA pipe).
// Loop 2 (A * x_new, 4-fma form, sign via XOR):
//   zacc_k      += ar*xre - ai*xim
//   zacc_{k+15} += ai*xre + ar*xim
__global__ void __launch_bounds__(TPB, 1) k_step(int emit_partials) {
    __shared__ u64 Ar2[Nn * GDC];
    __shared__ u64 Ai2[Nn * GDC];
    __shared__ u64 Am2[Nn * GDC];   // ar - ai
    int tid = threadIdx.x, gs = blockIdx.x;
    int g0 = gs * GDC;
    for (int i = tid; i < Nn * GDC; i += TPB) {
        int k = i / GDC, gl = i % GDC;
        int g = g0 + gl;
        float ar = (g < Gd) ? dA[k * G2 + g] : 0.0f;
        float ai = (g < Gd) ? dA[(k + Nn) * G2 + g] : 0.0f;
        Ar2[i] = pack2(ar, ar);
        Ai2[i] = pack2(ai, ai);
        float am = ar - ai;
        Am2[i] = pack2(am, am);
    }
    __syncthreads();
    int glN = Gd - g0;
    if (glN > GDC) glN = GDC;
    if (glN < 0) glN = 0;
    if (tid >= NACT) return;
    int c0 = tid * 2;

    // ---- loop 1: dense update of X (Karatsuba conjugate dot) ----
    {
        u64 zreg[K30];
        u64 zsum[Nn];
        #pragma unroll
        for (int k = 0; k < K30; k++)
            zreg[k] = *reinterpret_cast<const u64*>(&dZ[k * CP + c0]);
        #pragma unroll
        for (int k = 0; k < Nn; k++)
            zsum[k] = add2(zreg[k], zreg[k + Nn]);
        float thr = dParams[1];
        #pragma unroll 2
        for (int gl = 0; gl < glN; gl++) {
            int rowR = (g0 + gl) * CP + c0;
            int rowI = rowR + Gd * CP;
            float2 xr = *reinterpret_cast<const float2*>(&dX[rowR]);
            float2 xi = *reinterpret_cast<const float2*>(&dX[rowI]);
            float2 cr = *reinterpret_cast<const float2*>(&dC[rowR]);
            float2 ci = *reinterpret_cast<const float2*>(&dC[rowI]);
            u64 M1 = 0ULL, M2 = 0ULL, M3 = 0ULL;
            #pragma unroll
            for (int k = 0; k < Nn; k++) {
                M1 = fma2(Ar2[k * GDC + gl], zreg[k],      M1);
                M2 = fma2(Ai2[k * GDC + gl], zreg[k + Nn], M2);
                M3 = fma2(Am2[k * GDC + gl], zsum[k],      M3);
            }
            float m1a, m1b, m2a, m2b, m3a, m3b;
            unpack2(M1, m1a, m1b); unpack2(M2, m2a, m2b); unpack2(M3, m3a, m3b);
            float t0 = xr.x + cr.x - (m1a + m2a);
            float t1 = xr.y + cr.y - (m1b + m2b);
            float u0 = xi.x + ci.x - (m3a - m1a + m2a);
            float u1 = xi.y + ci.y - (m3b - m1b + m2b);
            float s0 = fmaxf(fabsf(t0) - thr, 0.0f);
            float s1 = fmaxf(fabsf(t1) - thr, 0.0f);
            float v0 = fmaxf(fabsf(u0) - thr, 0.0f);
            float v1 = fmaxf(fabsf(u1) - thr, 0.0f);
            float2 oR; oR.x = copysignf(s0, t0); oR.y = copysignf(s1, t1);
            float2 oI; oI.x = copysignf(v0, u0); oI.y = copysignf(v1, u1);
            *reinterpret_cast<float2*>(&dX[rowR]) = oR;
            *reinterpret_cast<float2*>(&dX[rowI]) = oI;
        }
    }

    // ---- loop 2: split-K partials of A * x_new ----
    if (emit_partials) {
        u64 zacc[K30];
        #pragma unroll
        for (int k = 0; k < K30; k++) zacc[k] = 0ULL;
        #pragma unroll 2
        for (int gl = 0; gl < glN; gl++) {
            int rowR = (g0 + gl) * CP + c0;
            int rowI = rowR + Gd * CP;
            u64 xre = *reinterpret_cast<const u64*>(&dX[rowR]);
            u64 xim = *reinterpret_cast<const u64*>(&dX[rowI]);
            u64 xnim = xim ^ 0x8000000080000000ULL;   // negate both packed floats
            #pragma unroll
            for (int k = 0; k < Nn; k++) {
                u64 arv = Ar2[k * GDC + gl];
                u64 aiv = Ai2[k * GDC + gl];
                zacc[k]      = fma2(arv, xre,  zacc[k]);
                zacc[k]      = fma2(aiv, xnim, zacc[k]);
                zacc[k + Nn] = fma2(aiv, xre,  zacc[k + Nn]);
                zacc[k + Nn] = fma2(arv, xim,  zacc[k + Nn]);
            }
        }
        float* zp = &dZpart[gs * (K30 * CP)];
        #pragma unroll
        for (int k = 0; k < K30; k++)
            *reinterpret_cast<u64*>(&zp[k * CP + c0]) = zacc[k];
    }
}

// reduce split-K partials, fold coef0: dZ = coef0 * sum_gs Zpart
// 4 lanes per element (gs mod 4), shfl tree combine -> quarter serial chain.
__global__ void k_zred() {
    int gid = blockIdx.x * 512 + threadIdx.x;   // 4 lanes per element
    int e = gid >> 2;
    int p = gid & 3;
    if (e >= K30 * CP) return;
    float s = 0.0f;
    #pragma unroll 4
    for (int gs = p; gs < GS; gs += 4) s += dZpart[gs * (K30 * CP) + e];
    s += __shfl_xor_sync(0xFFFFFFFFu, s, 1);
    s += __shfl_xor_sync(0xFFFFFFFFu, s, 2);
    if (p == 0) dZ[e] = s * dParams[0];
}

// ---------------- epilogue ----------------
__global__ void k_norms() {          // grid (4, 10), block 256
    int c = blockIdx.x * 256 + threadIdx.x;
    if (c >= CP) return;
    int j = blockIdx.y;
    int gstart = j * (Gd / 10);               // 484
    float s = 0.0f;
    for (int gl = 0; gl < Gd / 10; gl++) {
        int g = gstart + gl;
        float xr = dX[g * CP + c];
        float xi = dX[(g + Gd) * CP + c];
        s += sqrtf(xr * xr + xi * xi + 1e-12f);
    }
    dNpart[j * CP + c] = s;
}

__global__ void k_argmin() {         // <<<1,32>>>
    int b = threadIdx.x;
    if (b >= Bn) return;
    float best = 3.4e38f; int bi = 0;
    for (int t = 0; t < Tn; t++) {
        float v = 0.0f;
        for (int j = 0; j < 10; j++) v += dNpart[j * CP + b * Tn + t];
        if (v < best) { best = v; bi = t; }
    }
    dMinIdx[b] = bi;
}

__global__ void k_s(float* __restrict__ out) {   // grid (19, Bn), block 256
    __shared__ int cc[Bn];
    if (threadIdx.x < Bn) cc[threadIdx.x] = blockIdx.y * Tn + dMinIdx[threadIdx.x];
    __syncthreads();
    int g = blockIdx.x * 256 + threadIdx.x;
    int b = blockIdx.y;
    if (g >= Gd) return;
    float acc = 0.0f;
    #pragma unroll
    for (int bp = 0; bp < Bn; bp++) {
        int c = cc[bp];
        float xr = dX[g * CP + c];
        float xi = dX[(g + Gd) * CP + c];
        acc += sqrtf(xr * xr + xi * xi + 1e-12f);
    }
    out[64 + b * Gd + g] = acc * (1.0f / Bn);
}

__global__ void k_topk(const float* __restrict__ angles,
                       const float* __restrict__ ranges,
                       float* __restrict__ out) {  // <<<Bn,256>>>
    int b = blockIdx.x;
    const float* s = out + 64 + b * Gd;
    __shared__ float sv[256];
    __shared__ int   si[256];
    float bv = -3.4e38f; int bi = 0;
    for (int g = threadIdx.x; g < Gd; g += 256) {
        float v = s[g];
        if (v > bv || (v == bv && g < bi)) { bv = v; bi = g; }
    }
    sv[threadIdx.x] = bv; si[threadIdx.x] = bi;
    __syncthreads();
    for (int o = 128; o > 0; o >>= 1) {
        if (threadIdx.x < o) {
            float v2 = sv[threadIdx.x + o]; int i2 = si[threadIdx.x + o];
            if (v2 > sv[threadIdx.x] || (v2 == sv[threadIdx.x] && i2 < si[threadIdx.x])) {
                sv[threadIdx.x] = v2; si[threadIdx.x] = i2;
            }
        }
        __syncthreads();
    }
    int i1 = si[0];
    __syncthreads();
    bv = -3.4e38f; bi = 0;
    for (int g = threadIdx.x; g < Gd; g += 256) {
        if (g == i1) continue;
        float v = s[g];
        if (v > bv || (v == bv && g < bi)) { bv = v; bi = g; }
    }
    sv[threadIdx.x] = bv; si[threadIdx.x] = bi;
    __syncthreads();
    for (int o = 128; o > 0; o >>= 1) {
        if (threadIdx.x < o) {
            float v2 = sv[threadIdx.x + o]; int i2 = si[threadIdx.x + o];
            if (v2 > sv[threadIdx.x] || (v2 == sv[threadIdx.x] && i2 < si[threadIdx.x])) {
                sv[threadIdx.x] = v2; si[threadIdx.x] = i2;
            }
        }
        __syncthreads();
    }
    if (threadIdx.x == 0) {
        int i2 = si[0];
        out[b * 2 + 0]      = angles[i1 / NR];
        out[b * 2 + 1]      = angles[i2 / NR];
        out[32 + b * 2 + 0] = ranges[i1 % NR];
        out[32 + b * 2 + 1] = ranges[i2 % NR];
    }
}

// ---------------- launch ----------------
extern "C" void kernel_launch(void* const* d_in, const int* in_sizes, int n_in,
                              void* d_out, int out_size) {
    const float* y_real = (const float*)d_in[0];
    const float* y_imag = (const float*)d_in[1];
    const float* A_real = (const float*)d_in[2];
    const float* A_imag = (const float*)d_in[3];
    const float* angles = (const float*)d_in[4];
    const float* ranges = (const float*)d_in[5];
    float* out = (float*)d_out;

    void* pX = nullptr; cudaGetSymbolAddress(&pX, dX);
    void* pZ = nullptr; cudaGetSymbolAddress(&pZ, dZ);
    cudaMemsetAsync(pX, 0, sizeof(float) * (size_t)G2 * CP);
    cudaMemsetAsync(pZ, 0, sizeof(float) * (size_t)K30 * CP);

    k_build_yst<<<(K30 * CP + 255) / 256, 256>>>(y_real, y_imag);
    k_build_A<<<(K30 * G2 + 255) / 256, 256>>>(A_real, A_imag);
    k_gram_part<<<GS, 256>>>();
    k_gram_red<<<(K30 * K30 * 32 + 1023) / 1024, 1024>>>();
    k_eig<<<1, 1024>>>();

    k_buildC<<<GS, TPB>>>();

    for (int it = 0; it < NITER; it++) {
        int emit = (it < NITER - 1) ? 1 : 0;
        k_step<<<GS, TPB>>>(emit);
        if (emit)
            k_zred<<<(4 * K30 * CP + 511) / 512, 512>>>();
    }

    k_norms<<<dim3(4, 10), 256>>>();
    k_argmin<<<1, 32>>>();
    k_s<<<dim3((Gd + 255) / 256, Bn), 256>>>(out);
    k_topk<<<Bn, 256>>>(angles, ranges, out);
}

// round 15
// speedup vs baseline: 1.0616x; 1.0616x over previous
#include <cuda_runtime.h>
#include <math.h>

// ---------------- problem constants ----------------
#define Bn    16
#define Nn    15
#define Tn    50
#define NA    121
#define NR    40
#define Gd    4840            // NA*NR
#define G2    9680            // 2*Gd
#define K30   30              // 2*Nn
#define CP    800             // columns = B*T exactly
#define NITER 50
#define GS    148             // chunks (1 CTA/SM)
#define GDC   33              // Gd rows per chunk; 148*33=4884 >= 4840, tail masked
#define GCH   66              // buildC / gram: G2 rows per chunk
#define TPB   416             // 13 warps; threads 0..399 own 2 cols each
#define NACT  400             // active threads in main loops

typedef unsigned long long u64;

// ---------------- scratch (static device memory; no allocs) ----------------
__device__ float dA[K30 * G2];            // 1.16 MB  row-major [k][g]
__device__ float dX[G2 * CP];             // 31 MB  [g][c]
__device__ float dC[G2 * CP];             // 31 MB  [g][c]
__device__ float dZ[K30 * CP];            // [k][c], pre-scaled by coef0
__device__ float dZpart[GS * K30 * CP];   // 14.2 MB split-K partials
__device__ float dYst[K30 * CP];          // stacked y [k][c]
__device__ float dM30[K30 * K30];         // Gram A A^T
__device__ float dGpart[GS * K30 * K30];  // gram partials
__device__ float dParams[4];              // [0]=coef0=1/lambda, [1]=thr=0.3/lambda
__device__ float dNpart[10 * CP];         // norm partials
__device__ int   dMinIdx[Bn];

// ---------------- f32x2 helpers ----------------
__device__ __forceinline__ u64 pack2(float a, float b) {
    u64 r; asm("mov.b64 %0, {%1,%2};" : "=l"(r) : "f"(a), "f"(b)); return r;
}
__device__ __forceinline__ void unpack2(u64 v, float& a, float& b) {
    asm("mov.b64 {%0,%1}, %2;" : "=f"(a), "=f"(b) : "l"(v));
}
__device__ __forceinline__ u64 fma2(u64 a, u64 b, u64 c) {
    u64 d; asm("fma.rn.f32x2 %0, %1, %2, %3;" : "=l"(d) : "l"(a), "l"(b), "l"(c)); return d;
}
__device__ __forceinline__ u64 add2(u64 a, u64 b) {
    u64 d; asm("add.rn.f32x2 %0, %1, %2;" : "=l"(d) : "l"(a), "l"(b)); return d;
}

// ---------------- prep kernels ----------------
__global__ void k_build_yst(const float* __restrict__ yr, const float* __restrict__ yi) {
    int idx = blockIdx.x * 256 + threadIdx.x;       // over K30*CP = 24000
    if (idx >= K30 * CP) return;
    int k = idx / CP, c = idx % CP;
    int b = c / Tn, t = c % Tn;
    float v;
    if (k < Nn) v = yr[(b * Nn + k) * Tn + t];
    else        v = yi[(b * Nn + (k - Nn)) * Tn + t];
    dYst[idx] = v;
}

__global__ void k_build_A(const float* __restrict__ Ar, const float* __restrict__ Ai) {
    int idx = blockIdx.x * 256 + threadIdx.x;       // over K30*G2
    if (idx >= K30 * G2) return;
    int k = idx / G2, g = idx % G2;
    float v;
    if (k < Nn) {
        v = (g < Gd) ? Ar[k * Gd + g] : -Ai[k * Gd + (g - Gd)];
    } else {
        int kk = k - Nn;
        v = (g < Gd) ? Ai[kk * Gd + g] : Ar[kk * Gd + (g - Gd)];
    }
    dA[idx] = v;
}

// Gram stage 1: per-chunk partial 30x30 Gram (grid GS, block 256)
__global__ void k_gram_part() {
    __shared__ float As[K30 * GCH];
    int tid = threadIdx.x, gs = blockIdx.x;
    int g0 = gs * GCH;
    for (int i = tid; i < K30 * GCH; i += 256) {
        int k = i / GCH, gl = i % GCH;
        int g = g0 + gl;
        As[i] = (g < G2) ? dA[k * G2 + g] : 0.0f;
    }
    __syncthreads();
    for (int p = tid; p < K30 * K30; p += 256) {
        int i = p / K30, j = p % K30;
        float s = 0.0f;
        #pragma unroll 6
        for (int gl = 0; gl < GCH; gl++)
            s += As[i * GCH + gl] * As[j * GCH + gl];
        dGpart[gs * (K30 * K30) + p] = s;
    }
}

// Gram stage 2: one warp per element, lanes split the 148 partials (shfl tree)
__global__ void k_gram_red() {
    int warp = (blockIdx.x * blockDim.x + threadIdx.x) >> 5;
    int lane = threadIdx.x & 31;
    if (warp >= K30 * K30) return;
    float s = 0.0f;
    for (int gs = lane; gs < GS; gs += 32)
        s += dGpart[gs * (K30 * K30) + warp];
    #pragma unroll
    for (int o = 16; o > 0; o >>= 1)
        s += __shfl_xor_sync(0xFFFFFFFFu, s, o);
    if (lane == 0) dM30[warp] = s;
}

// lambda_max via 12 matrix squarings (Frobenius-normalized) + Rayleigh quotient
__global__ void k_eig() {
    __shared__ float Ms[900];
    __shared__ float Mn[900];
    __shared__ float wsum[32];
    __shared__ float norm2;
    int t = threadIdx.x;
    int lane = t & 31, wid = t >> 5;
    if (t < 900) Ms[t] = dM30[t];
    __syncthreads();
    for (int it = 0; it < 12; it++) {
        float v = 0.0f;
        if (t < 900) {
            int i = t / K30, j = t % K30;
            #pragma unroll 6
            for (int k = 0; k < K30; k++) v += Ms[i * K30 + k] * Ms[k * K30 + j];
            Mn[t] = v;
        }
        float w = (t < 900) ? v * v : 0.0f;
        #pragma unroll
        for (int o = 16; o > 0; o >>= 1)
            w += __shfl_xor_sync(0xFFFFFFFFu, w, o);
        if (lane == 0) wsum[wid] = w;
        __syncthreads();
        if (wid == 0) {
            float x = wsum[lane];
            #pragma unroll
            for (int o = 16; o > 0; o >>= 1)
                x += __shfl_xor_sync(0xFFFFFFFFu, x, o);
            if (lane == 0) norm2 = x;
        }
        __syncthreads();
        float inv = rsqrtf(norm2);
        if (t < 900) Ms[t] = Mn[t] * inv;
        __syncthreads();
    }
    if (t == 0) {
        float v[K30]; float nv = 0.0f;
        for (int i = 0; i < K30; i++) {
            float s = 0.0f;
            for (int j = 0; j < K30; j++) s += Ms[i * K30 + j];
            v[i] = s; nv += s * s;
        }
        float inv = rsqrtf(nv);
        for (int i = 0; i < K30; i++) v[i] *= inv;
        float lam = 0.0f;
        for (int i = 0; i < K30; i++) {
            float w = 0.0f;
            for (int j = 0; j < K30; j++) w += dM30[i * K30 + j] * v[j];
            lam += v[i] * w;
        }
        dParams[0] = 1.0f / lam;   // coef0 = step/n
        dParams[1] = 0.3f / lam;   // thr  = mu*step
    }
}

// C = coef0 * A^T yst : grid GS, block TPB (one-time, G2-chunked)
__global__ void __launch_bounds__(TPB, 1) k_buildC() {
    __shared__ u64 As2[K30 * GCH];
    int tid = threadIdx.x, gs = blockIdx.x;
    int g0 = gs * GCH;
    for (int i = tid; i < K30 * GCH; i += TPB) {
        int k = i / GCH, gl = i % GCH;
        int g = g0 + gl;
        float a = (g < G2) ? dA[k * G2 + g] : 0.0f;
        As2[i] = pack2(a, a);
    }
    __syncthreads();
    int glN = G2 - g0;
    if (glN > GCH) glN = GCH;
    if (glN < 0) glN = 0;
    if (tid >= NACT) return;
    int c0 = tid * 2;
    u64 yreg[K30];
    #pragma unroll
    for (int k = 0; k < K30; k++)
        yreg[k] = *reinterpret_cast<const u64*>(&dYst[k * CP + c0]);
    float coef0 = dParams[0];
    for (int gl = 0; gl < glN; gl++) {
        u64 d0 = 0ULL, d1 = 0ULL;
        #pragma unroll
        for (int k = 0; k < K30; k += 2) {
            d0 = fma2(As2[k * GCH + gl],       yreg[k],     d0);
            d1 = fma2(As2[(k + 1) * GCH + gl], yreg[k + 1], d1);
        }
        float a0, b0, a1, b1;
        unpack2(d0, a0, b0); unpack2(d1, a1, b1);
        float2 ov; ov.x = coef0 * (a0 + a1); ov.y = coef0 * (b0 + b1);
        *reinterpret_cast<float2*>(&dC[(g0 + gl) * CP + c0]) = ov;
    }
}

// ---------------- fused iteration kernel (complex-paired, Karatsuba loop1) ----------------
// Loop 1 (conjugate dot, 3-mult Karatsuba):
//   d(g)    = M1 + M2,          M1 = sum ar*zr,  M2 = sum ai*zi
//   d(g+Gd) = M3 - M1 + M2,     M3 = sum (ar-ai)*(zr+zi)
//   -> 45 fma2/gl instead of 60 (25% off the FMA pipe).
// Loop 2 (A * x_new, 4-fma form, sign via XOR):
//   zacc_k      += ar*xre - ai*xim
//   zacc_{k+15} += ai*xre + ar*xim
__global__ void __launch_bounds__(TPB, 1) k_step(int emit_partials) {
    __shared__ u64 Ar2[Nn * GDC];
    __shared__ u64 Ai2[Nn * GDC];
    __shared__ u64 Am2[Nn * GDC];   // ar - ai
    int tid = threadIdx.x, gs = blockIdx.x;
    int g0 = gs * GDC;
    for (int i = tid; i < Nn * GDC; i += TPB) {
        int k = i / GDC, gl = i % GDC;
        int g = g0 + gl;
        float ar = (g < Gd) ? dA[k * G2 + g] : 0.0f;
        float ai = (g < Gd) ? dA[(k + Nn) * G2 + g] : 0.0f;
        Ar2[i] = pack2(ar, ar);
        Ai2[i] = pack2(ai, ai);
        float am = ar - ai;
        Am2[i] = pack2(am, am);
    }
    __syncthreads();
    int glN = Gd - g0;
    if (glN > GDC) glN = GDC;
    if (glN < 0) glN = 0;
    if (tid >= NACT) return;
    int c0 = tid * 2;

    // ---- loop 1: dense update of X (Karatsuba conjugate dot) ----
    {
        u64 zreg[K30];
        u64 zsum[Nn];
        #pragma unroll
        for (int k = 0; k < K30; k++)
            zreg[k] = *reinterpret_cast<const u64*>(&dZ[k * CP + c0]);
        #pragma unroll
        for (int k = 0; k < Nn; k++)
            zsum[k] = add2(zreg[k], zreg[k + Nn]);
        float thr = dParams[1];
        #pragma unroll 2
        for (int gl = 0; gl < glN; gl++) {
            int rowR = (g0 + gl) * CP + c0;
            int rowI = rowR + Gd * CP;
            float2 xr = *reinterpret_cast<const float2*>(&dX[rowR]);
            float2 xi = *reinterpret_cast<const float2*>(&dX[rowI]);
            float2 cr = *reinterpret_cast<const float2*>(&dC[rowR]);
            float2 ci = *reinterpret_cast<const float2*>(&dC[rowI]);
            u64 M1 = 0ULL, M2 = 0ULL, M3 = 0ULL;
            #pragma unroll
            for (int k = 0; k < Nn; k++) {
                M1 = fma2(Ar2[k * GDC + gl], zreg[k],      M1);
                M2 = fma2(Ai2[k * GDC + gl], zreg[k + Nn], M2);
                M3 = fma2(Am2[k * GDC + gl], zsum[k],      M3);
            }
            float m1a, m1b, m2a, m2b, m3a, m3b;
            unpack2(M1, m1a, m1b); unpack2(M2, m2a, m2b); unpack2(M3, m3a, m3b);
            float t0 = xr.x + cr.x - (m1a + m2a);
            float t1 = xr.y + cr.y - (m1b + m2b);
            float u0 = xi.x + ci.x - (m3a - m1a + m2a);
            float u1 = xi.y + ci.y - (m3b - m1b + m2b);
            float s0 = fmaxf(fabsf(t0) - thr, 0.0f);
            float s1 = fmaxf(fabsf(t1) - thr, 0.0f);
            float v0 = fmaxf(fabsf(u0) - thr, 0.0f);
            float v1 = fmaxf(fabsf(u1) - thr, 0.0f);
            float2 oR; oR.x = copysignf(s0, t0); oR.y = copysignf(s1, t1);
            float2 oI; oI.x = copysignf(v0, u0); oI.y = copysignf(v1, u1);
            *reinterpret_cast<float2*>(&dX[rowR]) = oR;
            *reinterpret_cast<float2*>(&dX[rowI]) = oI;
        }
    }

    // ---- loop 2: split-K partials of A * x_new ----
    if (emit_partials) {
        u64 zacc[K30];
        #pragma unroll
        for (int k = 0; k < K30; k++) zacc[k] = 0ULL;
        #pragma unroll 2
        for (int gl = 0; gl < glN; gl++) {
            int rowR = (g0 + gl) * CP + c0;
            int rowI = rowR + Gd * CP;
            u64 xre = *reinterpret_cast<const u64*>(&dX[rowR]);
            u64 xim = *reinterpret_cast<const u64*>(&dX[rowI]);
            u64 xnim = xim ^ 0x8000000080000000ULL;   // negate both packed floats
            #pragma unroll
            for (int k = 0; k < Nn; k++) {
                u64 arv = Ar2[k * GDC + gl];
                u64 aiv = Ai2[k * GDC + gl];
                zacc[k]      = fma2(arv, xre,  zacc[k]);
                zacc[k]      = fma2(aiv, xnim, zacc[k]);
                zacc[k + Nn] = fma2(aiv, xre,  zacc[k + Nn]);
                zacc[k + Nn] = fma2(arv, xim,  zacc[k + Nn]);
            }
        }
        float* zp = &dZpart[gs * (K30 * CP)];
        #pragma unroll
        for (int k = 0; k < K30; k++)
            *reinterpret_cast<u64*>(&zp[k * CP + c0]) = zacc[k];
    }
}

// reduce split-K partials, fold coef0: dZ = coef0 * sum_gs Zpart
// 4 lanes per element (gs mod 4), shfl tree combine -> quarter serial chain.
__global__ void k_zred() {
    int gid = blockIdx.x * 512 + threadIdx.x;   // 4 lanes per element
    int e = gid >> 2;
    int p = gid & 3;
    if (e >= K30 * CP) return;
    float s = 0.0f;
    #pragma unroll 4
    for (int gs = p; gs < GS; gs += 4) s += dZpart[gs * (K30 * CP) + e];
    s += __shfl_xor_sync(0xFFFFFFFFu, s, 1);
    s += __shfl_xor_sync(0xFFFFFFFFu, s, 2);
    if (p == 0) dZ[e] = s * dParams[0];
}

// ---------------- epilogue ----------------
__global__ void k_norms() {          // grid (4, 10), block 256
    int c = blockIdx.x * 256 + threadIdx.x;
    if (c >= CP) return;
    int j = blockIdx.y;
    int gstart = j * (Gd / 10);               // 484
    float s = 0.0f;
    for (int gl = 0; gl < Gd / 10; gl++) {
        int g = gstart + gl;
        float xr = dX[g * CP + c];
        float xi = dX[(g + Gd) * CP + c];
        s += sqrtf(xr * xr + xi * xi + 1e-12f);
    }
    dNpart[j * CP + c] = s;
}

__global__ void k_argmin() {         // <<<1,32>>>
    int b = threadIdx.x;
    if (b >= Bn) return;
    float best = 3.4e38f; int bi = 0;
    for (int t = 0; t < Tn; t++) {
        float v = 0.0f;
        for (int j = 0; j < 10; j++) v += dNpart[j * CP + b * Tn + t];
        if (v < best) { best = v; bi = t; }
    }
    dMinIdx[b] = bi;
}

__global__ void k_s(float* __restrict__ out) {   // grid (19, Bn), block 256
    __shared__ int cc[Bn];
    if (threadIdx.x < Bn) cc[threadIdx.x] = blockIdx.y * Tn + dMinIdx[threadIdx.x];
    __syncthreads();
    int g = blockIdx.x * 256 + threadIdx.x;
    int b = blockIdx.y;
    if (g >= Gd) return;
    float acc = 0.0f;
    #pragma unroll
    for (int bp = 0; bp < Bn; bp++) {
        int c = cc[bp];
        float xr = dX[g * CP + c];
        float xi = dX[(g + Gd) * CP + c];
        acc += sqrtf(xr * xr + xi * xi + 1e-12f);
    }
    out[64 + b * Gd + g] = acc * (1.0f / Bn);
}

__global__ void k_topk(const float* __restrict__ angles,
                       const float* __restrict__ ranges,
                       float* __restrict__ out) {  // <<<Bn,256>>>
    int b = blockIdx.x;
    const float* s = out + 64 + b * Gd;
    __shared__ float sv[256];
    __shared__ int   si[256];
    float bv = -3.4e38f; int bi = 0;
    for (int g = threadIdx.x; g < Gd; g += 256) {
        float v = s[g];
        if (v > bv || (v == bv && g < bi)) { bv = v; bi = g; }
    }
    sv[threadIdx.x] = bv; si[threadIdx.x] = bi;
    __syncthreads();
    for (int o = 128; o > 0; o >>= 1) {
        if (threadIdx.x < o) {
            float v2 = sv[threadIdx.x + o]; int i2 = si[threadIdx.x + o];
            if (v2 > sv[threadIdx.x] || (v2 == sv[threadIdx.x] && i2 < si[threadIdx.x])) {
                sv[threadIdx.x] = v2; si[threadIdx.x] = i2;
            }
        }
        __syncthreads();
    }
    int i1 = si[0];
    __syncthreads();
    bv = -3.4e38f; bi = 0;
    for (int g = threadIdx.x; g < Gd; g += 256) {
        if (g == i1) continue;
        float v = s[g];
        if (v > bv || (v == bv && g < bi)) { bv = v; bi = g; }
    }
    sv[threadIdx.x] = bv; si[threadIdx.x] = bi;
    __syncthreads();
    for (int o = 128; o > 0; o >>= 1) {
        if (threadIdx.x < o) {
            float v2 = sv[threadIdx.x + o]; int i2 = si[threadIdx.x + o];
            if (v2 > sv[threadIdx.x] || (v2 == sv[threadIdx.x] && i2 < si[threadIdx.x])) {
                sv[threadIdx.x] = v2; si[threadIdx.x] = i2;
            }
        }
        __syncthreads();
    }
    if (threadIdx.x == 0) {
        int i2 = si[0];
        out[b * 2 + 0]      = angles[i1 / NR];
        out[b * 2 + 1]      = angles[i2 / NR];
        out[32 + b * 2 + 0] = ranges[i1 % NR];
        out[32 + b * 2 + 1] = ranges[i2 % NR];
    }
}

// ---------------- launch ----------------
extern "C" void kernel_launch(void* const* d_in, const int* in_sizes, int n_in,
                              void* d_out, int out_size) {
    const float* y_real = (const float*)d_in[0];
    const float* y_imag = (const float*)d_in[1];
    const float* A_real = (const float*)d_in[2];
    const float* A_imag = (const float*)d_in[3];
    const float* angles = (const float*)d_in[4];
    const float* ranges = (const float*)d_in[5];
    float* out = (float*)d_out;

    void* pX = nullptr; cudaGetSymbolAddress(&pX, dX);
    void* pZ = nullptr; cudaGetSymbolAddress(&pZ, dZ);
    cudaMemsetAsync(pX, 0, sizeof(float) * (size_t)G2 * CP);
    cudaMemsetAsync(pZ, 0, sizeof(float) * (size_t)K30 * CP);

    k_build_yst<<<(K30 * CP + 255) / 256, 256>>>(y_real, y_imag);
    k_build_A<<<(K30 * G2 + 255) / 256, 256>>>(A_real, A_imag);
    k_gram_part<<<GS, 256>>>();
    k_gram_red<<<(K30 * K30 * 32 + 1023) / 1024, 1024>>>();
    k_eig<<<1, 1024>>>();

    k_buildC<<<GS, TPB>>>();

    for (int it = 0; it < NITER; it++) {
        int emit = (it < NITER - 1) ? 1 : 0;
        k_step<<<GS, TPB>>>(emit);
        if (emit)
            k_zred<<<(4 * K30 * CP + 511) / 512, 512>>>();
    }

    k_norms<<<dim3(4, 10), 256>>>();
    k_argmin<<<1, 32>>>();
    k_s<<<dim3((Gd + 255) / 256, Bn), 256>>>(out);
    k_topk<<<Bn, 256>>>(angles, ranges, out);
}